// round 15
// baseline (speedup 1.0000x reference)
#include <cuda_runtime.h>
#include <cuda_bf16.h>

// y[i] = dot(x[i, 0:32], w[0:32]) + w[32]
//
// FINAL — memory-roofline-closed. Mandatory 528 MB one-pass stream sustained
// at 6.88-6.99 TB/s (~87% of HBM3e spec; kernel-internal 78.2-79.2 us vs
// ~76 us ideal at the measured ceiling). All controllable axes swept to
// neutrality under pre-registered predictions (R3-R14): load width 128/256b,
// MLP window 4/8/12 KB/warp, occupancy 21-83%, streaming/cached stores,
// grid geometry; the persistent-loop variant regressed 28% (WAR recycling).
//
// Structure: one-shot warps, each handling 64 rows (2 blocks of 32).
//  - Phase 1: all 16 coalesced streaming LDG.128 (8 KB/warp) front-batched
//    before any consumer (MLP=16/warp).
//  - Phase 2: per-load dot (FMA chain) + 3x shfl_xor butterfly within each
//    8-lane group (sum replicated across the group).
//  - Phase 3: register transpose via one shfl -> coalesced 128B cached store
//    per 32-row block (y L2-resident, writeback deferred past the reads).
__global__ void __launch_bounds__(256, 3)
linreg_kernel(const float4* __restrict__ x4,
              const float*  __restrict__ w,
              float*        __restrict__ y,
              int n)
{
    const int lane = threadIdx.x & 31;
    const int lig  = lane & 7;

    const int warp = blockIdx.x * (blockDim.x >> 5) + (threadIdx.x >> 5);
    const int row0 = warp << 6;                 // 64 rows per warp
    if (row0 >= n) return;

    const float4 wv  = __ldg(reinterpret_cast<const float4*>(w) + lig);
    const float bias = __ldg(w + 32);

    const float4* base = x4 + (size_t)row0 * 8 + lane;

    // ---- all 16 loads in flight before any consumer ----
    float4 a0 = __ldcs(base +  0 * 32);
    float4 a1 = __ldcs(base +  1 * 32);
    float4 a2 = __ldcs(base +  2 * 32);
    float4 a3 = __ldcs(base +  3 * 32);
    float4 a4 = __ldcs(base +  4 * 32);
    float4 a5 = __ldcs(base +  5 * 32);
    float4 a6 = __ldcs(base +  6 * 32);
    float4 a7 = __ldcs(base +  7 * 32);
    float4 b0 = __ldcs(base +  8 * 32);
    float4 b1 = __ldcs(base +  9 * 32);
    float4 b2 = __ldcs(base + 10 * 32);
    float4 b3 = __ldcs(base + 11 * 32);
    float4 b4 = __ldcs(base + 12 * 32);
    float4 b5 = __ldcs(base + 13 * 32);
    float4 b6 = __ldcs(base + 14 * 32);
    float4 b7 = __ldcs(base + 15 * 32);

#define DOT_RED(S, V)                                                          \
    float S = fmaf((V).x, wv.x,                                                \
              fmaf((V).y, wv.y, fmaf((V).z, wv.z, (V).w * wv.w)));             \
    S += __shfl_xor_sync(0xffffffffu, S, 4);                                   \
    S += __shfl_xor_sync(0xffffffffu, S, 2);                                   \
    S += __shfl_xor_sync(0xffffffffu, S, 1);

    const int src = ((lane & 3) << 3) | (lane >> 2);  // transpose source lane

    // ---- block A: rows row0 .. row0+31 ----
    {
        DOT_RED(s0, a0) DOT_RED(s1, a1) DOT_RED(s2, a2) DOT_RED(s3, a3)
        DOT_RED(s4, a4) DOT_RED(s5, a5) DOT_RED(s6, a6) DOT_RED(s7, a7)
        float val = s0;
        val = (lig == 1) ? s1 : val;
        val = (lig == 2) ? s2 : val;
        val = (lig == 3) ? s3 : val;
        val = (lig == 4) ? s4 : val;
        val = (lig == 5) ? s5 : val;
        val = (lig == 6) ? s6 : val;
        val = (lig == 7) ? s7 : val;
        float out = __shfl_sync(0xffffffffu, val, src) + bias;
        y[row0 + lane] = out;                 // coalesced 128B cached store
    }
    // ---- block B: rows row0+32 .. row0+63 ----
    {
        DOT_RED(s0, b0) DOT_RED(s1, b1) DOT_RED(s2, b2) DOT_RED(s3, b3)
        DOT_RED(s4, b4) DOT_RED(s5, b5) DOT_RED(s6, b6) DOT_RED(s7, b7)
        float val = s0;
        val = (lig == 1) ? s1 : val;
        val = (lig == 2) ? s2 : val;
        val = (lig == 3) ? s3 : val;
        val = (lig == 4) ? s4 : val;
        val = (lig == 5) ? s5 : val;
        val = (lig == 6) ? s6 : val;
        val = (lig == 7) ? s7 : val;
        float out = __shfl_sync(0xffffffffu, val, src) + bias;
        y[row0 + 32 + lane] = out;            // coalesced 128B cached store
    }
#undef DOT_RED
}

extern "C" void kernel_launch(void* const* d_in, const int* in_sizes, int n_in,
                              void* d_out, int out_size)
{
    const float* x = (const float*)d_in[0];   // [N, 32] fp32
    const float* w = (const float*)d_in[1];   // [33, 1] fp32
    float* y = (float*)d_out;                 // [N] fp32

    const int n = in_sizes[0] / 32;           // rows
    const int threads = 256;                  // 8 warps -> 512 rows per block
    const int rows_per_block = (threads / 32) * 64;
    const int blocks = (n + rows_per_block - 1) / rows_per_block;
    linreg_kernel<<<blocks, threads>>>(
        reinterpret_cast<const float4*>(x), w, y, n);
}

// round 16
// speedup vs baseline: 1.0087x; 1.0087x over previous
#include <cuda_runtime.h>
#include <cuda_bf16.h>

// y[i] = dot(x[i, 0:32], w[0:32]) + w[32]
//
// FINAL — memory-roofline-closed. Mandatory 528 MB one-pass stream sustained
// at 6.88-7.01 TB/s (~87-88% of HBM3e spec; kernel-internal 77.7-79.2 us vs
// ~76 us ideal at the measured ceiling). All controllable axes swept to
// neutrality under pre-registered predictions (R3-R15): load width 128/256b,
// MLP window 4/8/12 KB/warp, occupancy 21-83%, streaming/cached stores,
// grid geometry; the persistent-loop variant regressed 28% (WAR recycling).
//
// Structure: one-shot warps, each handling 64 rows (2 blocks of 32).
//  - Phase 1: all 16 coalesced streaming LDG.128 (8 KB/warp) front-batched
//    before any consumer (MLP=16/warp).
//  - Phase 2: per-load dot (FMA chain) + 3x shfl_xor butterfly within each
//    8-lane group (sum replicated across the group).
//  - Phase 3: register transpose via one shfl -> coalesced 128B cached store
//    per 32-row block (y L2-resident, writeback deferred past the reads).
__global__ void __launch_bounds__(256, 3)
linreg_kernel(const float4* __restrict__ x4,
              const float*  __restrict__ w,
              float*        __restrict__ y,
              int n)
{
    const int lane = threadIdx.x & 31;
    const int lig  = lane & 7;

    const int warp = blockIdx.x * (blockDim.x >> 5) + (threadIdx.x >> 5);
    const int row0 = warp << 6;                 // 64 rows per warp
    if (row0 >= n) return;

    const float4 wv  = __ldg(reinterpret_cast<const float4*>(w) + lig);
    const float bias = __ldg(w + 32);

    const float4* base = x4 + (size_t)row0 * 8 + lane;

    // ---- all 16 loads in flight before any consumer ----
    float4 a0 = __ldcs(base +  0 * 32);
    float4 a1 = __ldcs(base +  1 * 32);
    float4 a2 = __ldcs(base +  2 * 32);
    float4 a3 = __ldcs(base +  3 * 32);
    float4 a4 = __ldcs(base +  4 * 32);
    float4 a5 = __ldcs(base +  5 * 32);
    float4 a6 = __ldcs(base +  6 * 32);
    float4 a7 = __ldcs(base +  7 * 32);
    float4 b0 = __ldcs(base +  8 * 32);
    float4 b1 = __ldcs(base +  9 * 32);
    float4 b2 = __ldcs(base + 10 * 32);
    float4 b3 = __ldcs(base + 11 * 32);
    float4 b4 = __ldcs(base + 12 * 32);
    float4 b5 = __ldcs(base + 13 * 32);
    float4 b6 = __ldcs(base + 14 * 32);
    float4 b7 = __ldcs(base + 15 * 32);

#define DOT_RED(S, V)                                                          \
    float S = fmaf((V).x, wv.x,                                                \
              fmaf((V).y, wv.y, fmaf((V).z, wv.z, (V).w * wv.w)));             \
    S += __shfl_xor_sync(0xffffffffu, S, 4);                                   \
    S += __shfl_xor_sync(0xffffffffu, S, 2);                                   \
    S += __shfl_xor_sync(0xffffffffu, S, 1);

    const int src = ((lane & 3) << 3) | (lane >> 2);  // transpose source lane

    // ---- block A: rows row0 .. row0+31 ----
    {
        DOT_RED(s0, a0) DOT_RED(s1, a1) DOT_RED(s2, a2) DOT_RED(s3, a3)
        DOT_RED(s4, a4) DOT_RED(s5, a5) DOT_RED(s6, a6) DOT_RED(s7, a7)
        float val = s0;
        val = (lig == 1) ? s1 : val;
        val = (lig == 2) ? s2 : val;
        val = (lig == 3) ? s3 : val;
        val = (lig == 4) ? s4 : val;
        val = (lig == 5) ? s5 : val;
        val = (lig == 6) ? s6 : val;
        val = (lig == 7) ? s7 : val;
        float out = __shfl_sync(0xffffffffu, val, src) + bias;
        y[row0 + lane] = out;                 // coalesced 128B cached store
    }
    // ---- block B: rows row0+32 .. row0+63 ----
    {
        DOT_RED(s0, b0) DOT_RED(s1, b1) DOT_RED(s2, b2) DOT_RED(s3, b3)
        DOT_RED(s4, b4) DOT_RED(s5, b5) DOT_RED(s6, b6) DOT_RED(s7, b7)
        float val = s0;
        val = (lig == 1) ? s1 : val;
        val = (lig == 2) ? s2 : val;
        val = (lig == 3) ? s3 : val;
        val = (lig == 4) ? s4 : val;
        val = (lig == 5) ? s5 : val;
        val = (lig == 6) ? s6 : val;
        val = (lig == 7) ? s7 : val;
        float out = __shfl_sync(0xffffffffu, val, src) + bias;
        y[row0 + 32 + lane] = out;            // coalesced 128B cached store
    }
#undef DOT_RED
}

extern "C" void kernel_launch(void* const* d_in, const int* in_sizes, int n_in,
                              void* d_out, int out_size)
{
    const float* x = (const float*)d_in[0];   // [N, 32] fp32
    const float* w = (const float*)d_in[1];   // [33, 1] fp32
    float* y = (float*)d_out;                 // [N] fp32

    const int n = in_sizes[0] / 32;           // rows
    const int threads = 256;                  // 8 warps -> 512 rows per block
    const int rows_per_block = (threads / 32) * 64;
    const int blocks = (n + rows_per_block - 1) / rows_per_block;
    linreg_kernel<<<blocks, threads>>>(
        reinterpret_cast<const float4*>(x), w, y, n);
}